// round 15
// baseline (speedup 1.0000x reference)
#include <cuda_runtime.h>
#include <cuda_bf16.h>
#include <math.h>
#include <stdint.h>

#define B_   2
#define T_   2048
#define D_   1024
#define NH_  16
#define HD_  64
#define BT_  (B_*T_)      // 4096
#define NDH_ (NH_*HD_)    // 1024
#define K2_  (D_/2)       // 512
#define BN_  (B_*NH_)     // 32

// Scratch (allocation-free: __device__ globals)
__device__ float g_qt[(size_t)BN_*T_*HD_];   // Q tf32 bits, prescaled  [bn][t][h]
__device__ float g_kt[(size_t)BN_*T_*HD_];   // K tf32 bits             [bn][t][h]
__device__ float g_v [(size_t)BN_*T_*HD_];   // V fp32                  [bn][t][h]
__device__ float g_vt[(size_t)BN_*HD_*T_];   // V^T tf32 bits           [bn][h][t]

// packed GEMM inputs: [m][kp] u32 = (bf16 even-k, bf16 odd-k)
__device__ uint32_t g_xq_h[(size_t)BT_*K2_], g_xq_l[(size_t)BT_*K2_];
__device__ uint32_t g_xk_h[(size_t)BT_*K2_], g_xk_l[(size_t)BT_*K2_];
__device__ uint32_t g_xv_h[(size_t)BT_*K2_], g_xv_l[(size_t)BT_*K2_];

// attention output, prepacked bf16 hi/lo pairs along (n,h): [4096][512] u32
__device__ uint32_t g_oh[(size_t)BT_*K2_], g_ol[(size_t)BT_*K2_];

// prepacked weights: [n_out][k/2] u32
__device__ uint32_t g_wq_hi[(size_t)NDH_*K2_], g_wq_lo[(size_t)NDH_*K2_];
__device__ uint32_t g_wk_hi[(size_t)NDH_*K2_], g_wk_lo[(size_t)NDH_*K2_];
__device__ uint32_t g_wv_hi[(size_t)NDH_*K2_], g_wv_lo[(size_t)NDH_*K2_];
__device__ uint32_t g_wp_hi[(size_t)D_*K2_],   g_wp_lo[(size_t)D_*K2_];

#define QSCALE (0.125f * 1.4426950408889634f)

// ---------------------------------------------------------------------------
// helpers. ldsm4 MUST stay volatile (its smem read is invisible to the
// constraint list — round-10 bug). mma wrappers non-volatile (pure reg ops).
// ---------------------------------------------------------------------------
__device__ __forceinline__ uint32_t f2tf32(float x) {
    uint32_t r;
    asm("cvt.rna.tf32.f32 %0, %1;" : "=r"(r) : "f"(x));
    return r;
}

__device__ __forceinline__ float ex2(float x) {
    float r;
    asm("ex2.approx.f32 %0, %1;" : "=f"(r) : "f"(x));
    return r;
}

__device__ __forceinline__ uint32_t smaddr(const void* p) {
    return (uint32_t)__cvta_generic_to_shared(p);
}

__device__ __forceinline__ void ldsm4(uint32_t& r0, uint32_t& r1,
                                      uint32_t& r2, uint32_t& r3, uint32_t a) {
    asm volatile("ldmatrix.sync.aligned.m8n8.x4.shared.b16 {%0,%1,%2,%3}, [%4];"
                 : "=r"(r0), "=r"(r1), "=r"(r2), "=r"(r3) : "r"(a));
}

__device__ __forceinline__ void cpasync16(uint32_t s, const void* g) {
    asm volatile("cp.async.ca.shared.global [%0], [%1], 16;" :: "r"(s), "l"(g) : "memory");
}
__device__ __forceinline__ void cp_commit() {
    asm volatile("cp.async.commit_group;" ::: "memory");
}
__device__ __forceinline__ void cp_wait0() {
    asm volatile("cp.async.wait_group 0;" ::: "memory");
}

__device__ __forceinline__ void mma_tf32(float* c,
                                         uint32_t a0, uint32_t a1, uint32_t a2, uint32_t a3,
                                         uint32_t b0, uint32_t b1) {
    asm("mma.sync.aligned.m16n8k8.row.col.f32.tf32.tf32.f32 "
        "{%0,%1,%2,%3}, {%4,%5,%6,%7}, {%8,%9}, {%0,%1,%2,%3};"
        : "+f"(c[0]), "+f"(c[1]), "+f"(c[2]), "+f"(c[3])
        : "r"(a0), "r"(a1), "r"(a2), "r"(a3), "r"(b0), "r"(b1));
}

__device__ __forceinline__ void mma_bf16(float* c,
                                         uint32_t a0, uint32_t a1, uint32_t a2, uint32_t a3,
                                         uint32_t b0, uint32_t b1) {
    asm("mma.sync.aligned.m16n8k16.row.col.f32.bf16.bf16.f32 "
        "{%0,%1,%2,%3}, {%4,%5,%6,%7}, {%8,%9}, {%0,%1,%2,%3};"
        : "+f"(c[0]), "+f"(c[1]), "+f"(c[2]), "+f"(c[3])
        : "r"(a0), "r"(a1), "r"(a2), "r"(a3), "r"(b0), "r"(b1));
}

__device__ __forceinline__ void split2(float e, float o, uint32_t& hi, uint32_t& lo) {
    __nv_bfloat162 h = __floats2bfloat162_rn(e, o);
    float he = __low2float(h), ho = __high2float(h);
    __nv_bfloat162 l = __floats2bfloat162_rn(e - he, o - ho);
    hi = *reinterpret_cast<uint32_t*>(&h);
    lo = *reinterpret_cast<uint32_t*>(&l);
}

// ---------------------------------------------------------------------------
// Prepack GEMM inputs q/k/v [M][K] fp32 -> hi/lo [M][K/2] u32.  z selects.
// ---------------------------------------------------------------------------
__global__ void prepack_in_kernel(const float* __restrict__ Aq,
                                  const float* __restrict__ Ak,
                                  const float* __restrict__ Av)
{
    const int z = blockIdx.z;
    const float* A = (z == 0) ? Aq : (z == 1) ? Ak : Av;
    uint32_t* hi = (z == 0) ? g_xq_h : (z == 1) ? g_xk_h : g_xv_h;
    uint32_t* lo = (z == 0) ? g_xq_l : (z == 1) ? g_xk_l : g_xv_l;
    int idx = blockIdx.x * blockDim.x + threadIdx.x;
    if (idx >= BT_ * K2_) return;
    float2 v = *(const float2*)(A + (size_t)idx * 2);
    uint32_t h, l;
    split2(v.x, v.y, h, l);
    hi[idx] = h;
    lo[idx] = l;
}

// ---------------------------------------------------------------------------
// Prepack QKV weights W [K][N] fp32 -> hi/lo [N][K/2] u32.  z selects q/k/v.
// ---------------------------------------------------------------------------
__global__ void prepack_wqkv_kernel(const float* __restrict__ Wq,
                                    const float* __restrict__ Wk,
                                    const float* __restrict__ Wv)
{
    const int z = blockIdx.z;
    const float* W = (z == 0) ? Wq : (z == 1) ? Wk : Wv;
    uint32_t* hi = (z == 0) ? g_wq_hi : (z == 1) ? g_wk_hi : g_wv_hi;
    uint32_t* lo = (z == 0) ? g_wq_lo : (z == 1) ? g_wk_lo : g_wv_lo;
    int idx = blockIdx.x * blockDim.x + threadIdx.x;
    if (idx >= NDH_ * K2_) return;
    int kp = idx & (K2_ - 1);
    int n  = idx >> 9;
    float e = W[(size_t)(2 * kp) * NDH_ + n];
    float o = W[(size_t)(2 * kp + 1) * NDH_ + n];
    uint32_t h, l;
    split2(e, o, h, l);
    hi[(size_t)n * K2_ + kp] = h;
    lo[(size_t)n * K2_ + kp] = l;
}

// ---------------------------------------------------------------------------
// Prepack w_projection [N, D, H] -> hi/lo [d][(n,h)/2] u32
// ---------------------------------------------------------------------------
__global__ void prepack_wpt_kernel(const float* __restrict__ wp)
{
    int idx = blockIdx.x * blockDim.x + threadIdx.x;
    if (idx >= D_ * K2_) return;
    int kp = idx & (K2_ - 1);
    int d  = idx >> 9;
    int n  = kp >> 5;
    int hp = kp & 31;
    const float* base = wp + ((size_t)n * D_ + d) * HD_ + 2 * hp;
    float e = base[0], o = base[1];
    uint32_t h, l;
    split2(e, o, h, l);
    g_wp_hi[(size_t)d * K2_ + kp] = h;
    g_wp_lo[(size_t)d * K2_ + kp] = l;
}

// ---------------------------------------------------------------------------
// Prepack V: [bn][t][h] fp32 -> [bn][h][t] tf32 bits (transpose).
// ---------------------------------------------------------------------------
__global__ __launch_bounds__(256)
void prepack_v_kernel()
{
    __shared__ float sm[64][65];
    const int bn = blockIdx.y;
    const int tt = blockIdx.x;          // t-tile of 64
    const int tid = threadIdx.x;
    const float* Vg = g_v + ((size_t)bn * T_ + tt * 64) * HD_;

    #pragma unroll
    for (int i = 0; i < 4; i++) {
        int lin = tid + i * 256;
        int r = lin >> 4, c4 = (lin & 15) << 2;
        float4 v = *(const float4*)(Vg + r * HD_ + c4);
        sm[r][c4 + 0] = v.x; sm[r][c4 + 1] = v.y;
        sm[r][c4 + 2] = v.z; sm[r][c4 + 3] = v.w;
    }
    __syncthreads();

    #pragma unroll
    for (int i = 0; i < 4; i++) {
        int lin = tid + i * 256;
        int h = lin >> 4, t4 = (lin & 15) << 2;
        float4 v;
        v.x = __uint_as_float(f2tf32(sm[t4 + 0][h]));
        v.y = __uint_as_float(f2tf32(sm[t4 + 1][h]));
        v.z = __uint_as_float(f2tf32(sm[t4 + 2][h]));
        v.w = __uint_as_float(f2tf32(sm[t4 + 3][h]));
        *(float4*)(g_vt + ((size_t)bn * HD_ + h) * T_ + tt * 64 + t4) = v;
    }
}

// ---------------------------------------------------------------------------
// bf16-split tensor-core GEMM: all operands prepacked, cp.async staging,
// zero conversion math in the loop. 128x128 tile, BK=16 (8 kpairs), 8 warps.
// MODE 0: tf32 bits out [b,n,t,h], scaled    (Q with QSCALE, K with 1.0)
// MODE 1: fp32 out [M][Ncols] row-major       (out-proj)
// MODE 2: fp32 out [b,n,t,h]                  (V)
// ---------------------------------------------------------------------------
template<int MODE>
__device__ __forceinline__ void gemm_core(const uint32_t* __restrict__ Ahi,
                                          const uint32_t* __restrict__ Alo,
                                          const uint32_t* __restrict__ Bhi,
                                          const uint32_t* __restrict__ Blo,
                                          const float* __restrict__ bias,
                                          float* __restrict__ C,
                                          float scale,
                                          int M, int K, int Ncols)
{
    __shared__ uint32_t AsHi[2][128 * 12];
    __shared__ uint32_t AsLo[2][128 * 12];
    __shared__ uint32_t BsHi[2][128 * 12];
    __shared__ uint32_t BsLo[2][128 * 12];

    const int tid  = threadIdx.x;
    const int warp = tid >> 5;
    const int lane = tid & 31;
    const int g    = lane >> 2;
    const int tig  = lane & 3;
    const int wm   = warp >> 2;
    const int wn   = warp & 3;
    const int m0   = blockIdx.y * 128;
    const int n0   = blockIdx.x * 128;
    const int Kp   = K >> 1;

    const int lrow  = tid >> 1;
    const int lhalf = tid & 1;

    const int arow = (lane & 7) + ((lane >> 3) & 1) * 8;
    const int akp  = (lane >> 4) * 4;
    const int brow = (lane & 7) + ((lane >> 4) & 1) * 8;
    const int bkp  = ((lane >> 3) & 1) * 4;

    const uint32_t ash = smaddr(AsHi), asl = smaddr(AsLo);
    const uint32_t bsh = smaddr(BsHi), bsl = smaddr(BsLo);
    const uint32_t a_fo = ((arow) * 12 + akp) * 4;
    const uint32_t b_fo = ((brow) * 12 + bkp) * 4;

    const uint32_t soff = (uint32_t)(lrow * 12 + lhalf * 4) * 4;
    const uint32_t STG  = 128 * 12 * 4;   // stage stride in bytes
    const size_t a_base = (size_t)(m0 + lrow) * Kp + lhalf * 4;
    const size_t b_base = (size_t)(n0 + lrow) * Kp + lhalf * 4;

    float acc[4][4][4];
    #pragma unroll
    for (int i = 0; i < 4; i++)
        #pragma unroll
        for (int j = 0; j < 4; j++)
            #pragma unroll
            for (int e = 0; e < 4; e++)
                acc[i][j][e] = 0.0f;

    auto issue = [&](int k0, int st) {
        const int kq = k0 >> 1;
        cpasync16(ash + st * STG + soff, Ahi + a_base + kq);
        cpasync16(asl + st * STG + soff, Alo + a_base + kq);
        cpasync16(bsh + st * STG + soff, Bhi + b_base + kq);
        cpasync16(bsl + st * STG + soff, Blo + b_base + kq);
        cp_commit();
    };

    auto compute = [&](int st) {
        const uint32_t sto = st * STG;
        uint32_t bh[4][2], bl[4][2];
        #pragma unroll
        for (int nt2 = 0; nt2 < 2; nt2++) {
            const uint32_t ro = (wn * 32 + nt2 * 16) * 12 * 4;
            ldsm4(bh[nt2*2][0], bh[nt2*2][1], bh[nt2*2+1][0], bh[nt2*2+1][1],
                  bsh + sto + ro + b_fo);
            ldsm4(bl[nt2*2][0], bl[nt2*2][1], bl[nt2*2+1][0], bl[nt2*2+1][1],
                  bsl + sto + ro + b_fo);
        }
        #pragma unroll
        for (int mt = 0; mt < 4; mt++) {
            const uint32_t ro = (wm * 64 + mt * 16) * 12 * 4;
            uint32_t ah0, ah1, ah2, ah3, al0, al1, al2, al3;
            ldsm4(ah0, ah1, ah2, ah3, ash + sto + ro + a_fo);
            ldsm4(al0, al1, al2, al3, asl + sto + ro + a_fo);
            #pragma unroll
            for (int nt = 0; nt < 4; nt++)
                mma_bf16(acc[mt][nt], ah0, ah1, ah2, ah3, bh[nt][0], bh[nt][1]);
            #pragma unroll
            for (int nt = 0; nt < 4; nt++)
                mma_bf16(acc[mt][nt], ah0, ah1, ah2, ah3, bl[nt][0], bl[nt][1]);
            #pragma unroll
            for (int nt = 0; nt < 4; nt++)
                mma_bf16(acc[mt][nt], al0, al1, al2, al3, bh[nt][0], bh[nt][1]);
        }
    };

    // 2-stage cp.async pipeline, one syncthreads per k-tile
    issue(0, 0);
    int st = 0;
    for (int k0 = 16; k0 < K; k0 += 16) {
        cp_wait0();
        __syncthreads();      // stage st ready for all; st^1 free of readers
        issue(k0, st ^ 1);    // loads fly under compute
        compute(st);
        st ^= 1;
    }
    cp_wait0();
    __syncthreads();
    compute(st);

    #pragma unroll
    for (int mt = 0; mt < 4; mt++) {
        #pragma unroll
        for (int nt = 0; nt < 4; nt++) {
            const int cbase = n0 + wn * 32 + nt * 8 + tig * 2;
            const int mg = m0 + wm * 64 + mt * 16 + g;
            #pragma unroll
            for (int e = 0; e < 4; e++) {
                const int m  = mg + ((e >= 2) ? 8 : 0);
                const int cc = cbase + (e & 1);
                float val = acc[mt][nt][e] + bias[cc];
                if (MODE == 0) {
                    int b = m >> 11, t = m & (T_ - 1);
                    int n = cc >> 6, h = cc & 63;
                    C[(((size_t)b * NH_ + n) * T_ + t) * HD_ + h] =
                        __uint_as_float(f2tf32(val * scale));
                } else if (MODE == 2) {
                    int b = m >> 11, t = m & (T_ - 1);
                    int n = cc >> 6, h = cc & 63;
                    C[(((size_t)b * NH_ + n) * T_ + t) * HD_ + h] = val;
                } else {
                    C[(size_t)m * Ncols + cc] = val;
                }
            }
        }
    }
}

// Batched QKV projection: z=0 Q (tf32 bits, prescaled), z=1 K, z=2 V fp32
__global__ __launch_bounds__(256)
void gemm_qkv_kernel(const float* __restrict__ bq, const float* __restrict__ bk,
                     const float* __restrict__ bv)
{
    const int z = blockIdx.z;
    if (z == 0)
        gemm_core<0>(g_xq_h, g_xq_l, g_wq_hi, g_wq_lo, bq, g_qt, QSCALE, BT_, D_, NDH_);
    else if (z == 1)
        gemm_core<0>(g_xk_h, g_xk_l, g_wk_hi, g_wk_lo, bk, g_kt, 1.0f, BT_, D_, NDH_);
    else
        gemm_core<2>(g_xv_h, g_xv_l, g_wv_hi, g_wv_lo, bv, g_v, 1.0f, BT_, D_, NDH_);
}

__global__ __launch_bounds__(256)
void gemm_out_kernel(const float* __restrict__ bias, float* __restrict__ C)
{
    gemm_core<1>(g_oh, g_ol, g_wp_hi, g_wp_lo, bias, C, 1.0f, BT_, NDH_, D_);
}

// ---------------------------------------------------------------------------
// tf32 flash attention, prepacked inputs + ldmatrix fragments (r14, passing).
// ---------------------------------------------------------------------------
__global__ __launch_bounds__(256, 2)
void attn_tc_kernel()
{
    extern __shared__ float smx[];
    float* Kt  = smx;                 // [64][68]
    float* VtT = smx + 64 * 68;       // [64][68]
    float* Pw  = VtT + 64 * 68;       // [128][68]

    const int tid  = threadIdx.x;
    const int warp = tid >> 5;
    const int lane = tid & 31;
    const int g    = lane >> 2;
    const int tig  = lane & 3;
    const int bn   = blockIdx.y;
    const int b    = bn / NH_;
    const int n    = bn % NH_;
    const int q0   = blockIdx.x * 128;
    const int wrow = warp * 16;

    const uint32_t kt_b = smaddr(Kt);
    const uint32_t vt_b = smaddr(VtT);
    const uint32_t pw_b = smaddr(Pw);

    const int arow = (lane & 7) + ((lane >> 3) & 1) * 8;
    const int ako  = (lane >> 4) * 4;
    const int brow = (lane & 7) + ((lane >> 4) & 1) * 8;
    const int bko  = ((lane >> 3) & 1) * 4;
    const uint32_t a_fo = (uint32_t)(arow * 68 + ako) * 4;
    const uint32_t b_fo = (uint32_t)(brow * 68 + bko) * 4;

    // persistent Q fragments: direct LDG from prescaled tf32 global
    uint32_t qf[8][4];
    {
        const float* Q0 = g_qt + ((size_t)bn * T_ + q0 + wrow + g) * HD_;
        const float* Q1 = Q0 + 8 * HD_;
        #pragma unroll
        for (int k8 = 0; k8 < 8; k8++) {
            qf[k8][0] = __float_as_uint(Q0[k8 * 8 + tig    ]);
            qf[k8][1] = __float_as_uint(Q1[k8 * 8 + tig    ]);
            qf[k8][2] = __float_as_uint(Q0[k8 * 8 + tig + 4]);
            qf[k8][3] = __float_as_uint(Q1[k8 * 8 + tig + 4]);
        }
    }

    const float* Kg  = g_kt + (size_t)bn * T_ * HD_;
    const float* Vtg = g_vt + (size_t)bn * HD_ * T_;

    float of[8][4];
    #pragma unroll
    for (int i = 0; i < 8; i++)
        #pragma unroll
        for (int e = 0; e < 4; e++) of[i][e] = 0.0f;
    float m0r = -1e30f, m1r = -1e30f;
    float l0r = 0.0f,   l1r = 0.0f;

    for (int s0 = 0; s0 < T_; s0 += 64) {
        __syncthreads();
        #pragma unroll
        for (int i = 0; i < 4; i++) {
            int idx = tid + i * 256;
            int r = idx >> 4, c4 = (idx & 15) << 2;
            *(float4*)&Kt[r * 68 + c4]  = *(const float4*)(Kg  + (size_t)(s0 + r) * HD_ + c4);
            *(float4*)&VtT[r * 68 + c4] = *(const float4*)(Vtg + (size_t)r * T_ + s0 + c4);
        }
        __syncthreads();

        // S = Q @ K^T (tf32), fragments via ldmatrix
        float sacc[8][4];
        #pragma unroll
        for (int i = 0; i < 8; i++)
            #pragma unroll
            for (int e = 0; e < 4; e++) sacc[i][e] = 0.0f;
        #pragma unroll
        for (int k8 = 0; k8 < 8; k8++) {
            #pragma unroll
            for (int nt2 = 0; nt2 < 4; nt2++) {
                const uint32_t off = (uint32_t)(nt2 * 16 * 68 + k8 * 8) * 4;
                uint32_t b0, b1, b2, b3;
                ldsm4(b0, b1, b2, b3, kt_b + off + b_fo);
                mma_tf32(sacc[2*nt2],   qf[k8][0], qf[k8][1], qf[k8][2], qf[k8][3], b0, b1);
                mma_tf32(sacc[2*nt2+1], qf[k8][0], qf[k8][1], qf[k8][2], qf[k8][3], b2, b3);
            }
        }

        // online softmax (base-2)
        float mx0 = -1e30f, mx1 = -1e30f;
        #pragma unroll
        for (int nt = 0; nt < 8; nt++) {
            mx0 = fmaxf(mx0, fmaxf(sacc[nt][0], sacc[nt][1]));
            mx1 = fmaxf(mx1, fmaxf(sacc[nt][2], sacc[nt][3]));
        }
        mx0 = fmaxf(mx0, __shfl_xor_sync(0xffffffffu, mx0, 1));
        mx0 = fmaxf(mx0, __shfl_xor_sync(0xffffffffu, mx0, 2));
        mx1 = fmaxf(mx1, __shfl_xor_sync(0xffffffffu, mx1, 1));
        mx1 = fmaxf(mx1, __shfl_xor_sync(0xffffffffu, mx1, 2));
        float nm0 = fmaxf(m0r, mx0), nm1 = fmaxf(m1r, mx1);
        float cr0 = ex2(m0r - nm0), cr1 = ex2(m1r - nm1);
        m0r = nm0; m1r = nm1;

        float sum0 = 0.0f, sum1 = 0.0f;
        #pragma unroll
        for (int nt = 0; nt < 8; nt++) {
            sacc[nt][0] = ex2(sacc[nt][0] - nm0);
            sacc[nt][1] = ex2(sacc[nt][1] - nm0);
            sacc[nt][2] = ex2(sacc[nt][2] - nm1);
            sacc[nt][3] = ex2(sacc[nt][3] - nm1);
            sum0 += sacc[nt][0] + sacc[nt][1];
            sum1 += sacc[nt][2] + sacc[nt][3];
        }
        sum0 += __shfl_xor_sync(0xffffffffu, sum0, 1);
        sum0 += __shfl_xor_sync(0xffffffffu, sum0, 2);
        sum1 += __shfl_xor_sync(0xffffffffu, sum1, 1);
        sum1 += __shfl_xor_sync(0xffffffffu, sum1, 2);
        l0r = l0r * cr0 + sum0;
        l1r = l1r * cr1 + sum1;
        #pragma unroll
        for (int nt = 0; nt < 8; nt++) {
            of[nt][0] *= cr0; of[nt][1] *= cr0;
            of[nt][2] *= cr1; of[nt][3] *= cr1;
        }

        // store P (tf32 bits) into this warp's own rows of Pw
        #pragma unroll
        for (int nt = 0; nt < 8; nt++) {
            float2 v01, v23;
            v01.x = __uint_as_float(f2tf32(sacc[nt][0]));
            v01.y = __uint_as_float(f2tf32(sacc[nt][1]));
            v23.x = __uint_as_float(f2tf32(sacc[nt][2]));
            v23.y = __uint_as_float(f2tf32(sacc[nt][3]));
            *(float2*)&Pw[(wrow + g    ) * 68 + nt * 8 + tig * 2] = v01;
            *(float2*)&Pw[(wrow + g + 8) * 68 + nt * 8 + tig * 2] = v23;
        }
        __syncwarp();

        // O += P @ V
        #pragma unroll
        for (int k8 = 0; k8 < 8; k8++) {
            uint32_t a0, a1, a2, a3;
            ldsm4(a0, a1, a2, a3,
                  pw_b + (uint32_t)(wrow * 68 * 4) + (uint32_t)(k8 * 32) + a_fo);
            #pragma unroll
            for (int nt2 = 0; nt2 < 4; nt2++) {
                const uint32_t off = (uint32_t)(nt2 * 16 * 68 + k8 * 8) * 4;
                uint32_t v0, v1, v2, v3;
                ldsm4(v0, v1, v2, v3, vt_b + off + b_fo);
                mma_tf32(of[2*nt2],   a0, a1, a2, a3, v0, v1);
                mma_tf32(of[2*nt2+1], a0, a1, a2, a3, v2, v3);
            }
        }
    }

    // epilogue: normalize, pack bf16 hi/lo pairs, write [m][(n,h)/2]
    const float inv0 = 1.0f / l0r;
    const float inv1 = 1.0f / l1r;
    const int t0 = q0 + wrow + g;
    const size_t m0row = (size_t)(b * T_ + t0) * K2_;
    const size_t m1row = (size_t)(b * T_ + t0 + 8) * K2_;
    #pragma unroll
    for (int nt = 0; nt < 8; nt++) {
        const int kp = n * 32 + nt * 4 + tig;
        uint32_t h0, l0, h1, l1;
        split2(of[nt][0] * inv0, of[nt][1] * inv0, h0, l0);
        split2(of[nt][2] * inv1, of[nt][3] * inv1, h1, l1);
        g_oh[m0row + kp] = h0;  g_ol[m0row + kp] = l0;
        g_oh[m1row + kp] = h1;  g_ol[m1row + kp] = l1;
    }
}

// ---------------------------------------------------------------------------
// Launch
// Inputs: 0:q 1:v 2:k 3:w_query 4:b_query 5:w_value 6:b_value 7:w_key 8:b_key
//         9:w_projection 10:b_projection
// ---------------------------------------------------------------------------
extern "C" void kernel_launch(void* const* d_in, const int* in_sizes, int n_in,
                              void* d_out, int out_size)
{
    const float* q_in = (const float*)d_in[0];
    const float* v_in = (const float*)d_in[1];
    const float* k_in = (const float*)d_in[2];
    const float* w_q  = (const float*)d_in[3];
    const float* b_q  = (const float*)d_in[4];
    const float* w_v  = (const float*)d_in[5];
    const float* b_v  = (const float*)d_in[6];
    const float* w_k  = (const float*)d_in[7];
    const float* b_k  = (const float*)d_in[8];
    const float* w_p  = (const float*)d_in[9];
    const float* b_p  = (const float*)d_in[10];
    float* out = (float*)d_out;

    const int ATTN_SMEM = (64 * 68 + 64 * 68 + 128 * 68) * 4;   // 69632 B
    cudaFuncSetAttribute(attn_tc_kernel,
                         cudaFuncAttributeMaxDynamicSharedMemorySize, ATTN_SMEM);

    // 1. prepack weights + inputs (bf16 hi/lo pairs)
    dim3 wgrid((NDH_ * K2_) / 256, 1, 3);
    prepack_wqkv_kernel<<<wgrid, 256>>>(w_q, w_k, w_v);
    prepack_wpt_kernel<<<(D_ * K2_) / 256, 256>>>(w_p);
    dim3 igrid((BT_ * K2_) / 256, 1, 3);
    prepack_in_kernel<<<igrid, 256>>>(q_in, k_in, v_in);

    // 2. QKV projections (all operands prepacked; cp.async pipeline)
    dim3 ggrid(NDH_ / 128, BT_ / 128, 3);
    gemm_qkv_kernel<<<ggrid, 256>>>(b_q, b_k, b_v);

    // 3. prepack V (transpose to [bn][h][t] tf32 bits)
    dim3 vgrid(T_ / 64, BN_);
    prepack_v_kernel<<<vgrid, 256>>>();

    // 4. attention (tf32, ldmatrix fragments, packed bf16 output)
    dim3 agrid(T_ / 128, BN_);
    attn_tc_kernel<<<agrid, 256, ATTN_SMEM>>>();

    // 5. output projection
    dim3 pgrid(D_ / 128, BT_ / 128);
    gemm_out_kernel<<<pgrid, 256>>>(b_p, out);
}

// round 16
// speedup vs baseline: 1.3934x; 1.3934x over previous
#include <cuda_runtime.h>
#include <cuda_bf16.h>
#include <math.h>
#include <stdint.h>

#define B_   2
#define T_   2048
#define D_   1024
#define NH_  16
#define HD_  64
#define BT_  (B_*T_)      // 4096
#define NDH_ (NH_*HD_)    // 1024
#define K2_  (D_/2)       // 512
#define BN_  (B_*NH_)     // 32

// Scratch (allocation-free: __device__ globals)
__device__ float g_qt[(size_t)BN_*T_*HD_];   // Q tf32 bits, prescaled  [bn][t][h]
__device__ float g_kt[(size_t)BN_*T_*HD_];   // K tf32 bits             [bn][t][h]
__device__ float g_v [(size_t)BN_*T_*HD_];   // V fp32                  [bn][t][h]
__device__ float g_vt[(size_t)BN_*HD_*T_];   // V^T tf32 bits           [bn][h][t]

// packed GEMM inputs: [m][kp] u32 = (bf16 even-k, bf16 odd-k)
__device__ uint32_t g_xq_h[(size_t)BT_*K2_], g_xq_l[(size_t)BT_*K2_];
__device__ uint32_t g_xk_h[(size_t)BT_*K2_], g_xk_l[(size_t)BT_*K2_];
__device__ uint32_t g_xv_h[(size_t)BT_*K2_], g_xv_l[(size_t)BT_*K2_];

// attention output, prepacked bf16 hi/lo pairs along (n,h): [4096][512] u32
__device__ uint32_t g_oh[(size_t)BT_*K2_], g_ol[(size_t)BT_*K2_];

// prepacked weights: [n_out][k/2] u32
__device__ uint32_t g_wq_hi[(size_t)NDH_*K2_], g_wq_lo[(size_t)NDH_*K2_];
__device__ uint32_t g_wk_hi[(size_t)NDH_*K2_], g_wk_lo[(size_t)NDH_*K2_];
__device__ uint32_t g_wv_hi[(size_t)NDH_*K2_], g_wv_lo[(size_t)NDH_*K2_];
__device__ uint32_t g_wp_hi[(size_t)D_*K2_],   g_wp_lo[(size_t)D_*K2_];

#define QSCALE (0.125f * 1.4426950408889634f)

// ---------------------------------------------------------------------------
// helpers. ldsm4 MUST stay volatile (its smem read is invisible to the
// constraint list — round-10 bug). mma wrappers non-volatile (pure reg ops).
// NO cp.async anywhere: B300 LDGSTS break-even is N>=32 per thread; our depth
// is 4 — measured 1.5x regression in round 15. Register LDG prefetch only.
// ---------------------------------------------------------------------------
__device__ __forceinline__ uint32_t f2tf32(float x) {
    uint32_t r;
    asm("cvt.rna.tf32.f32 %0, %1;" : "=r"(r) : "f"(x));
    return r;
}

__device__ __forceinline__ float ex2(float x) {
    float r;
    asm("ex2.approx.f32 %0, %1;" : "=f"(r) : "f"(x));
    return r;
}

__device__ __forceinline__ uint32_t smaddr(const void* p) {
    return (uint32_t)__cvta_generic_to_shared(p);
}

__device__ __forceinline__ void ldsm4(uint32_t& r0, uint32_t& r1,
                                      uint32_t& r2, uint32_t& r3, uint32_t a) {
    asm volatile("ldmatrix.sync.aligned.m8n8.x4.shared.b16 {%0,%1,%2,%3}, [%4];"
                 : "=r"(r0), "=r"(r1), "=r"(r2), "=r"(r3) : "r"(a));
}

__device__ __forceinline__ void mma_tf32(float* c,
                                         uint32_t a0, uint32_t a1, uint32_t a2, uint32_t a3,
                                         uint32_t b0, uint32_t b1) {
    asm("mma.sync.aligned.m16n8k8.row.col.f32.tf32.tf32.f32 "
        "{%0,%1,%2,%3}, {%4,%5,%6,%7}, {%8,%9}, {%0,%1,%2,%3};"
        : "+f"(c[0]), "+f"(c[1]), "+f"(c[2]), "+f"(c[3])
        : "r"(a0), "r"(a1), "r"(a2), "r"(a3), "r"(b0), "r"(b1));
}

__device__ __forceinline__ void mma_bf16(float* c,
                                         uint32_t a0, uint32_t a1, uint32_t a2, uint32_t a3,
                                         uint32_t b0, uint32_t b1) {
    asm("mma.sync.aligned.m16n8k16.row.col.f32.bf16.bf16.f32 "
        "{%0,%1,%2,%3}, {%4,%5,%6,%7}, {%8,%9}, {%0,%1,%2,%3};"
        : "+f"(c[0]), "+f"(c[1]), "+f"(c[2]), "+f"(c[3])
        : "r"(a0), "r"(a1), "r"(a2), "r"(a3), "r"(b0), "r"(b1));
}

__device__ __forceinline__ void split2(float e, float o, uint32_t& hi, uint32_t& lo) {
    __nv_bfloat162 h = __floats2bfloat162_rn(e, o);
    float he = __low2float(h), ho = __high2float(h);
    __nv_bfloat162 l = __floats2bfloat162_rn(e - he, o - ho);
    hi = *reinterpret_cast<uint32_t*>(&h);
    lo = *reinterpret_cast<uint32_t*>(&l);
}

// ---------------------------------------------------------------------------
// Prepack GEMM inputs q/k/v [M][K] fp32 -> hi/lo [M][K/2] u32.  z selects.
// ---------------------------------------------------------------------------
__global__ void prepack_in_kernel(const float* __restrict__ Aq,
                                  const float* __restrict__ Ak,
                                  const float* __restrict__ Av)
{
    const int z = blockIdx.z;
    const float* A = (z == 0) ? Aq : (z == 1) ? Ak : Av;
    uint32_t* hi = (z == 0) ? g_xq_h : (z == 1) ? g_xk_h : g_xv_h;
    uint32_t* lo = (z == 0) ? g_xq_l : (z == 1) ? g_xk_l : g_xv_l;
    int idx = blockIdx.x * blockDim.x + threadIdx.x;
    if (idx >= BT_ * K2_) return;
    float2 v = *(const float2*)(A + (size_t)idx * 2);
    uint32_t h, l;
    split2(v.x, v.y, h, l);
    hi[idx] = h;
    lo[idx] = l;
}

// ---------------------------------------------------------------------------
// Prepack QKV weights W [K][N] fp32 -> hi/lo [N][K/2] u32.  z selects q/k/v.
// ---------------------------------------------------------------------------
__global__ void prepack_wqkv_kernel(const float* __restrict__ Wq,
                                    const float* __restrict__ Wk,
                                    const float* __restrict__ Wv)
{
    const int z = blockIdx.z;
    const float* W = (z == 0) ? Wq : (z == 1) ? Wk : Wv;
    uint32_t* hi = (z == 0) ? g_wq_hi : (z == 1) ? g_wk_hi : g_wv_hi;
    uint32_t* lo = (z == 0) ? g_wq_lo : (z == 1) ? g_wk_lo : g_wv_lo;
    int idx = blockIdx.x * blockDim.x + threadIdx.x;
    if (idx >= NDH_ * K2_) return;
    int kp = idx & (K2_ - 1);
    int n  = idx >> 9;
    float e = W[(size_t)(2 * kp) * NDH_ + n];
    float o = W[(size_t)(2 * kp + 1) * NDH_ + n];
    uint32_t h, l;
    split2(e, o, h, l);
    hi[(size_t)n * K2_ + kp] = h;
    lo[(size_t)n * K2_ + kp] = l;
}

// ---------------------------------------------------------------------------
// Prepack w_projection [N, D, H] -> hi/lo [d][(n,h)/2] u32
// ---------------------------------------------------------------------------
__global__ void prepack_wpt_kernel(const float* __restrict__ wp)
{
    int idx = blockIdx.x * blockDim.x + threadIdx.x;
    if (idx >= D_ * K2_) return;
    int kp = idx & (K2_ - 1);
    int d  = idx >> 9;
    int n  = kp >> 5;
    int hp = kp & 31;
    const float* base = wp + ((size_t)n * D_ + d) * HD_ + 2 * hp;
    float e = base[0], o = base[1];
    uint32_t h, l;
    split2(e, o, h, l);
    g_wp_hi[(size_t)d * K2_ + kp] = h;
    g_wp_lo[(size_t)d * K2_ + kp] = l;
}

// ---------------------------------------------------------------------------
// Prepack V: [bn][t][h] fp32 -> [bn][h][t] tf32 bits (transpose).
// ---------------------------------------------------------------------------
__global__ __launch_bounds__(256)
void prepack_v_kernel()
{
    __shared__ float sm[64][65];
    const int bn = blockIdx.y;
    const int tt = blockIdx.x;          // t-tile of 64
    const int tid = threadIdx.x;
    const float* Vg = g_v + ((size_t)bn * T_ + tt * 64) * HD_;

    #pragma unroll
    for (int i = 0; i < 4; i++) {
        int lin = tid + i * 256;
        int r = lin >> 4, c4 = (lin & 15) << 2;
        float4 v = *(const float4*)(Vg + r * HD_ + c4);
        sm[r][c4 + 0] = v.x; sm[r][c4 + 1] = v.y;
        sm[r][c4 + 2] = v.z; sm[r][c4 + 3] = v.w;
    }
    __syncthreads();

    #pragma unroll
    for (int i = 0; i < 4; i++) {
        int lin = tid + i * 256;
        int h = lin >> 4, t4 = (lin & 15) << 2;
        float4 v;
        v.x = __uint_as_float(f2tf32(sm[t4 + 0][h]));
        v.y = __uint_as_float(f2tf32(sm[t4 + 1][h]));
        v.z = __uint_as_float(f2tf32(sm[t4 + 2][h]));
        v.w = __uint_as_float(f2tf32(sm[t4 + 3][h]));
        *(float4*)(g_vt + ((size_t)bn * HD_ + h) * T_ + tt * 64 + t4) = v;
    }
}

// ---------------------------------------------------------------------------
// bf16-split tensor-core GEMM: ALL operands prepacked hi/lo [m][kp] u32.
// Register LDG prefetch (4x LDG.128) -> STS.128, double-buffered smem,
// one syncthreads per k-tile, ldmatrix fragments, zero conversion in loop.
// MODE 0: tf32 bits out [b,n,t,h], scaled    (Q with QSCALE, K with 1.0)
// MODE 1: fp32 out [M][Ncols] row-major       (out-proj)
// MODE 2: fp32 out [b,n,t,h]                  (V)
// ---------------------------------------------------------------------------
template<int MODE>
__device__ __forceinline__ void gemm_core(const uint32_t* __restrict__ Ahi,
                                          const uint32_t* __restrict__ Alo,
                                          const uint32_t* __restrict__ Bhi,
                                          const uint32_t* __restrict__ Blo,
                                          const float* __restrict__ bias,
                                          float* __restrict__ C,
                                          float scale,
                                          int M, int K, int Ncols)
{
    __shared__ uint32_t AsHi[2][128 * 12];
    __shared__ uint32_t AsLo[2][128 * 12];
    __shared__ uint32_t BsHi[2][128 * 12];
    __shared__ uint32_t BsLo[2][128 * 12];

    const int tid  = threadIdx.x;
    const int warp = tid >> 5;
    const int lane = tid & 31;
    const int g    = lane >> 2;
    const int tig  = lane & 3;
    const int wm   = warp >> 2;
    const int wn   = warp & 3;
    const int m0   = blockIdx.y * 128;
    const int n0   = blockIdx.x * 128;
    const int Kp   = K >> 1;

    const int lrow  = tid >> 1;
    const int lhalf = tid & 1;

    const int arow = (lane & 7) + ((lane >> 3) & 1) * 8;
    const int akp  = (lane >> 4) * 4;
    const int brow = (lane & 7) + ((lane >> 4) & 1) * 8;
    const int bkp  = ((lane >> 3) & 1) * 4;

    const uint32_t ash = smaddr(AsHi), asl = smaddr(AsLo);
    const uint32_t bsh = smaddr(BsHi), bsl = smaddr(BsLo);
    const uint32_t a_fo = ((arow) * 12 + akp) * 4;
    const uint32_t b_fo = ((brow) * 12 + bkp) * 4;

    const size_t a_base = (size_t)(m0 + lrow) * Kp + lhalf * 4;
    const size_t b_base = (size_t)(n0 + lrow) * Kp + lhalf * 4;
    const int    soff   = lrow * 12 + lhalf * 4;

    float acc[4][4][4];
    #pragma unroll
    for (int i = 0; i < 4; i++)
        #pragma unroll
        for (int j = 0; j < 4; j++)
            #pragma unroll
            for (int e = 0; e < 4; e++)
                acc[i][j][e] = 0.0f;

    uint4 arh, arl, brh, brl;

    auto gload = [&](int k0) {
        const int kq = k0 >> 1;
        arh = *(const uint4*)(Ahi + a_base + kq);
        arl = *(const uint4*)(Alo + a_base + kq);
        brh = *(const uint4*)(Bhi + b_base + kq);
        brl = *(const uint4*)(Blo + b_base + kq);
    };

    auto sstore = [&](int st) {
        *(uint4*)&AsHi[st][soff] = arh;
        *(uint4*)&AsLo[st][soff] = arl;
        *(uint4*)&BsHi[st][soff] = brh;
        *(uint4*)&BsLo[st][soff] = brl;
    };

    auto compute = [&](int st) {
        const uint32_t sto = st * (128 * 12 * 4);
        uint32_t bh[4][2], bl[4][2];
        #pragma unroll
        for (int nt2 = 0; nt2 < 2; nt2++) {
            const uint32_t ro = (wn * 32 + nt2 * 16) * 12 * 4;
            ldsm4(bh[nt2*2][0], bh[nt2*2][1], bh[nt2*2+1][0], bh[nt2*2+1][1],
                  bsh + sto + ro + b_fo);
            ldsm4(bl[nt2*2][0], bl[nt2*2][1], bl[nt2*2+1][0], bl[nt2*2+1][1],
                  bsl + sto + ro + b_fo);
        }
        #pragma unroll
        for (int mt = 0; mt < 4; mt++) {
            const uint32_t ro = (wm * 64 + mt * 16) * 12 * 4;
            uint32_t ah0, ah1, ah2, ah3, al0, al1, al2, al3;
            ldsm4(ah0, ah1, ah2, ah3, ash + sto + ro + a_fo);
            ldsm4(al0, al1, al2, al3, asl + sto + ro + a_fo);
            #pragma unroll
            for (int nt = 0; nt < 4; nt++)
                mma_bf16(acc[mt][nt], ah0, ah1, ah2, ah3, bh[nt][0], bh[nt][1]);
            #pragma unroll
            for (int nt = 0; nt < 4; nt++)
                mma_bf16(acc[mt][nt], ah0, ah1, ah2, ah3, bl[nt][0], bl[nt][1]);
            #pragma unroll
            for (int nt = 0; nt < 4; nt++)
                mma_bf16(acc[mt][nt], al0, al1, al2, al3, bh[nt][0], bh[nt][1]);
        }
    };

    gload(0);
    sstore(0);
    __syncthreads();

    int st = 0;
    for (int k0 = 16; k0 < K; k0 += 16) {
        gload(k0);          // prefetch next tile (LDGs fly under MMAs)
        compute(st);
        sstore(st ^ 1);
        __syncthreads();
        st ^= 1;
    }
    compute(st);

    #pragma unroll
    for (int mt = 0; mt < 4; mt++) {
        #pragma unroll
        for (int nt = 0; nt < 4; nt++) {
            const int cbase = n0 + wn * 32 + nt * 8 + tig * 2;
            const int mg = m0 + wm * 64 + mt * 16 + g;
            #pragma unroll
            for (int e = 0; e < 4; e++) {
                const int m  = mg + ((e >= 2) ? 8 : 0);
                const int cc = cbase + (e & 1);
                float val = acc[mt][nt][e] + bias[cc];
                if (MODE == 0) {
                    int b = m >> 11, t = m & (T_ - 1);
                    int n = cc >> 6, h = cc & 63;
                    C[(((size_t)b * NH_ + n) * T_ + t) * HD_ + h] =
                        __uint_as_float(f2tf32(val * scale));
                } else if (MODE == 2) {
                    int b = m >> 11, t = m & (T_ - 1);
                    int n = cc >> 6, h = cc & 63;
                    C[(((size_t)b * NH_ + n) * T_ + t) * HD_ + h] = val;
                } else {
                    C[(size_t)m * Ncols + cc] = val;
                }
            }
        }
    }
}

// Batched QKV projection: z=0 Q (tf32 bits, prescaled), z=1 K, z=2 V fp32
__global__ __launch_bounds__(256)
void gemm_qkv_kernel(const float* __restrict__ bq, const float* __restrict__ bk,
                     const float* __restrict__ bv)
{
    const int z = blockIdx.z;
    if (z == 0)
        gemm_core<0>(g_xq_h, g_xq_l, g_wq_hi, g_wq_lo, bq, g_qt, QSCALE, BT_, D_, NDH_);
    else if (z == 1)
        gemm_core<0>(g_xk_h, g_xk_l, g_wk_hi, g_wk_lo, bk, g_kt, 1.0f, BT_, D_, NDH_);
    else
        gemm_core<2>(g_xv_h, g_xv_l, g_wv_hi, g_wv_lo, bv, g_v, 1.0f, BT_, D_, NDH_);
}

__global__ __launch_bounds__(256)
void gemm_out_kernel(const float* __restrict__ bias, float* __restrict__ C)
{
    gemm_core<1>(g_oh, g_ol, g_wp_hi, g_wp_lo, bias, C, 1.0f, BT_, NDH_, D_);
}

// ---------------------------------------------------------------------------
// tf32 flash attention, prepacked inputs + ldmatrix fragments (r14, passing).
// ---------------------------------------------------------------------------
__global__ __launch_bounds__(256, 2)
void attn_tc_kernel()
{
    extern __shared__ float smx[];
    float* Kt  = smx;                 // [64][68]
    float* VtT = smx + 64 * 68;       // [64][68]
    float* Pw  = VtT + 64 * 68;       // [128][68]

    const int tid  = threadIdx.x;
    const int warp = tid >> 5;
    const int lane = tid & 31;
    const int g    = lane >> 2;
    const int tig  = lane & 3;
    const int bn   = blockIdx.y;
    const int b    = bn / NH_;
    const int n    = bn % NH_;
    const int q0   = blockIdx.x * 128;
    const int wrow = warp * 16;

    const uint32_t kt_b = smaddr(Kt);
    const uint32_t vt_b = smaddr(VtT);
    const uint32_t pw_b = smaddr(Pw);

    const int arow = (lane & 7) + ((lane >> 3) & 1) * 8;
    const int ako  = (lane >> 4) * 4;
    const int brow = (lane & 7) + ((lane >> 4) & 1) * 8;
    const int bko  = ((lane >> 3) & 1) * 4;
    const uint32_t a_fo = (uint32_t)(arow * 68 + ako) * 4;
    const uint32_t b_fo = (uint32_t)(brow * 68 + bko) * 4;

    // persistent Q fragments: direct LDG from prescaled tf32 global
    uint32_t qf[8][4];
    {
        const float* Q0 = g_qt + ((size_t)bn * T_ + q0 + wrow + g) * HD_;
        const float* Q1 = Q0 + 8 * HD_;
        #pragma unroll
        for (int k8 = 0; k8 < 8; k8++) {
            qf[k8][0] = __float_as_uint(Q0[k8 * 8 + tig    ]);
            qf[k8][1] = __float_as_uint(Q1[k8 * 8 + tig    ]);
            qf[k8][2] = __float_as_uint(Q0[k8 * 8 + tig + 4]);
            qf[k8][3] = __float_as_uint(Q1[k8 * 8 + tig + 4]);
        }
    }

    const float* Kg  = g_kt + (size_t)bn * T_ * HD_;
    const float* Vtg = g_vt + (size_t)bn * HD_ * T_;

    float of[8][4];
    #pragma unroll
    for (int i = 0; i < 8; i++)
        #pragma unroll
        for (int e = 0; e < 4; e++) of[i][e] = 0.0f;
    float m0r = -1e30f, m1r = -1e30f;
    float l0r = 0.0f,   l1r = 0.0f;

    for (int s0 = 0; s0 < T_; s0 += 64) {
        __syncthreads();
        #pragma unroll
        for (int i = 0; i < 4; i++) {
            int idx = tid + i * 256;
            int r = idx >> 4, c4 = (idx & 15) << 2;
            *(float4*)&Kt[r * 68 + c4]  = *(const float4*)(Kg  + (size_t)(s0 + r) * HD_ + c4);
            *(float4*)&VtT[r * 68 + c4] = *(const float4*)(Vtg + (size_t)r * T_ + s0 + c4);
        }
        __syncthreads();

        // S = Q @ K^T (tf32), fragments via ldmatrix
        float sacc[8][4];
        #pragma unroll
        for (int i = 0; i < 8; i++)
            #pragma unroll
            for (int e = 0; e < 4; e++) sacc[i][e] = 0.0f;
        #pragma unroll
        for (int k8 = 0; k8 < 8; k8++) {
            #pragma unroll
            for (int nt2 = 0; nt2 < 4; nt2++) {
                const uint32_t off = (uint32_t)(nt2 * 16 * 68 + k8 * 8) * 4;
                uint32_t b0, b1, b2, b3;
                ldsm4(b0, b1, b2, b3, kt_b + off + b_fo);
                mma_tf32(sacc[2*nt2],   qf[k8][0], qf[k8][1], qf[k8][2], qf[k8][3], b0, b1);
                mma_tf32(sacc[2*nt2+1], qf[k8][0], qf[k8][1], qf[k8][2], qf[k8][3], b2, b3);
            }
        }

        // online softmax (base-2)
        float mx0 = -1e30f, mx1 = -1e30f;
        #pragma unroll
        for (int nt = 0; nt < 8; nt++) {
            mx0 = fmaxf(mx0, fmaxf(sacc[nt][0], sacc[nt][1]));
            mx1 = fmaxf(mx1, fmaxf(sacc[nt][2], sacc[nt][3]));
        }
        mx0 = fmaxf(mx0, __shfl_xor_sync(0xffffffffu, mx0, 1));
        mx0 = fmaxf(mx0, __shfl_xor_sync(0xffffffffu, mx0, 2));
        mx1 = fmaxf(mx1, __shfl_xor_sync(0xffffffffu, mx1, 1));
        mx1 = fmaxf(mx1, __shfl_xor_sync(0xffffffffu, mx1, 2));
        float nm0 = fmaxf(m0r, mx0), nm1 = fmaxf(m1r, mx1);
        float cr0 = ex2(m0r - nm0), cr1 = ex2(m1r - nm1);
        m0r = nm0; m1r = nm1;

        float sum0 = 0.0f, sum1 = 0.0f;
        #pragma unroll
        for (int nt = 0; nt < 8; nt++) {
            sacc[nt][0] = ex2(sacc[nt][0] - nm0);
            sacc[nt][1] = ex2(sacc[nt][1] - nm0);
            sacc[nt][2] = ex2(sacc[nt][2] - nm1);
            sacc[nt][3] = ex2(sacc[nt][3] - nm1);
            sum0 += sacc[nt][0] + sacc[nt][1];
            sum1 += sacc[nt][2] + sacc[nt][3];
        }
        sum0 += __shfl_xor_sync(0xffffffffu, sum0, 1);
        sum0 += __shfl_xor_sync(0xffffffffu, sum0, 2);
        sum1 += __shfl_xor_sync(0xffffffffu, sum1, 1);
        sum1 += __shfl_xor_sync(0xffffffffu, sum1, 2);
        l0r = l0r * cr0 + sum0;
        l1r = l1r * cr1 + sum1;
        #pragma unroll
        for (int nt = 0; nt < 8; nt++) {
            of[nt][0] *= cr0; of[nt][1] *= cr0;
            of[nt][2] *= cr1; of[nt][3] *= cr1;
        }

        // store P (tf32 bits) into this warp's own rows of Pw
        #pragma unroll
        for (int nt = 0; nt < 8; nt++) {
            float2 v01, v23;
            v01.x = __uint_as_float(f2tf32(sacc[nt][0]));
            v01.y = __uint_as_float(f2tf32(sacc[nt][1]));
            v23.x = __uint_as_float(f2tf32(sacc[nt][2]));
            v23.y = __uint_as_float(f2tf32(sacc[nt][3]));
            *(float2*)&Pw[(wrow + g    ) * 68 + nt * 8 + tig * 2] = v01;
            *(float2*)&Pw[(wrow + g + 8) * 68 + nt * 8 + tig * 2] = v23;
        }
        __syncwarp();

        // O += P @ V
        #pragma unroll
        for (int k8 = 0; k8 < 8; k8++) {
            uint32_t a0, a1, a2, a3;
            ldsm4(a0, a1, a2, a3,
                  pw_b + (uint32_t)(wrow * 68 * 4) + (uint32_t)(k8 * 32) + a_fo);
            #pragma unroll
            for (int nt2 = 0; nt2 < 4; nt2++) {
                const uint32_t off = (uint32_t)(nt2 * 16 * 68 + k8 * 8) * 4;
                uint32_t v0, v1, v2, v3;
                ldsm4(v0, v1, v2, v3, vt_b + off + b_fo);
                mma_tf32(of[2*nt2],   a0, a1, a2, a3, v0, v1);
                mma_tf32(of[2*nt2+1], a0, a1, a2, a3, v2, v3);
            }
        }
    }

    // epilogue: normalize, pack bf16 hi/lo pairs, write [m][(n,h)/2]
    const float inv0 = 1.0f / l0r;
    const float inv1 = 1.0f / l1r;
    const int t0 = q0 + wrow + g;
    const size_t m0row = (size_t)(b * T_ + t0) * K2_;
    const size_t m1row = (size_t)(b * T_ + t0 + 8) * K2_;
    #pragma unroll
    for (int nt = 0; nt < 8; nt++) {
        const int kp = n * 32 + nt * 4 + tig;
        uint32_t h0, l0, h1, l1;
        split2(of[nt][0] * inv0, of[nt][1] * inv0, h0, l0);
        split2(of[nt][2] * inv1, of[nt][3] * inv1, h1, l1);
        g_oh[m0row + kp] = h0;  g_ol[m0row + kp] = l0;
        g_oh[m1row + kp] = h1;  g_ol[m1row + kp] = l1;
    }
}

// ---------------------------------------------------------------------------
// Launch
// Inputs: 0:q 1:v 2:k 3:w_query 4:b_query 5:w_value 6:b_value 7:w_key 8:b_key
//         9:w_projection 10:b_projection
// ---------------------------------------------------------------------------
extern "C" void kernel_launch(void* const* d_in, const int* in_sizes, int n_in,
                              void* d_out, int out_size)
{
    const float* q_in = (const float*)d_in[0];
    const float* v_in = (const float*)d_in[1];
    const float* k_in = (const float*)d_in[2];
    const float* w_q  = (const float*)d_in[3];
    const float* b_q  = (const float*)d_in[4];
    const float* w_v  = (const float*)d_in[5];
    const float* b_v  = (const float*)d_in[6];
    const float* w_k  = (const float*)d_in[7];
    const float* b_k  = (const float*)d_in[8];
    const float* w_p  = (const float*)d_in[9];
    const float* b_p  = (const float*)d_in[10];
    float* out = (float*)d_out;

    const int ATTN_SMEM = (64 * 68 + 64 * 68 + 128 * 68) * 4;   // 69632 B
    cudaFuncSetAttribute(attn_tc_kernel,
                         cudaFuncAttributeMaxDynamicSharedMemorySize, ATTN_SMEM);

    // 1. prepack weights + inputs (bf16 hi/lo pairs)
    dim3 wgrid((NDH_ * K2_) / 256, 1, 3);
    prepack_wqkv_kernel<<<wgrid, 256>>>(w_q, w_k, w_v);
    prepack_wpt_kernel<<<(D_ * K2_) / 256, 256>>>(w_p);
    dim3 igrid((BT_ * K2_) / 256, 1, 3);
    prepack_in_kernel<<<igrid, 256>>>(q_in, k_in, v_in);

    // 2. QKV projections (all operands prepacked; register LDG prefetch)
    dim3 ggrid(NDH_ / 128, BT_ / 128, 3);
    gemm_qkv_kernel<<<ggrid, 256>>>(b_q, b_k, b_v);

    // 3. prepack V (transpose to [bn][h][t] tf32 bits)
    dim3 vgrid(T_ / 64, BN_);
    prepack_v_kernel<<<vgrid, 256>>>();

    // 4. attention (tf32, ldmatrix fragments, packed bf16 output)
    dim3 agrid(T_ / 128, BN_);
    attn_tc_kernel<<<agrid, 256, ATTN_SMEM>>>();

    // 5. output projection
    dim3 pgrid(D_ / 128, BT_ / 128);
    gemm_out_kernel<<<pgrid, 256>>>(b_p, out);
}

// round 17
// speedup vs baseline: 1.4718x; 1.0562x over previous
#include <cuda_runtime.h>
#include <cuda_bf16.h>
#include <math.h>
#include <stdint.h>

#define B_   2
#define T_   2048
#define D_   1024
#define NH_  16
#define HD_  64
#define BT_  (B_*T_)      // 4096
#define NDH_ (NH_*HD_)    // 1024
#define K2_  (D_/2)       // 512
#define BN_  (B_*NH_)     // 32

// Scratch (allocation-free: __device__ globals)
__device__ float g_qt[(size_t)BN_*T_*HD_];   // Q tf32 bits, prescaled  [bn][t][h]
__device__ float g_kt[(size_t)BN_*T_*HD_];   // K tf32 bits             [bn][t][h]
__device__ float g_v [(size_t)BN_*T_*HD_];   // V fp32                  [bn][t][h]
__device__ float g_vt[(size_t)BN_*HD_*T_];   // V^T tf32 bits           [bn][h][t]

// packed GEMM inputs: [m][kp] u32 = (bf16 even-k, bf16 odd-k)
__device__ uint32_t g_xq_h[(size_t)BT_*K2_], g_xq_l[(size_t)BT_*K2_];
__device__ uint32_t g_xk_h[(size_t)BT_*K2_], g_xk_l[(size_t)BT_*K2_];
__device__ uint32_t g_xv_h[(size_t)BT_*K2_], g_xv_l[(size_t)BT_*K2_];

// attention output, prepacked bf16 hi/lo pairs along (n,h): [4096][512] u32
__device__ uint32_t g_oh[(size_t)BT_*K2_], g_ol[(size_t)BT_*K2_];

// prepacked weights: [n_out][k/2] u32
__device__ uint32_t g_wq_hi[(size_t)NDH_*K2_], g_wq_lo[(size_t)NDH_*K2_];
__device__ uint32_t g_wk_hi[(size_t)NDH_*K2_], g_wk_lo[(size_t)NDH_*K2_];
__device__ uint32_t g_wv_hi[(size_t)NDH_*K2_], g_wv_lo[(size_t)NDH_*K2_];
__device__ uint32_t g_wp_hi[(size_t)D_*K2_],   g_wp_lo[(size_t)D_*K2_];

#define QSCALE (0.125f * 1.4426950408889634f)

// ---------------------------------------------------------------------------
// helpers. ldsm4 MUST stay volatile (its smem read is invisible to the
// constraint list — round-10 bug). mma wrappers non-volatile (pure reg ops).
// NO cp.async (B300 LDGSTS break-even N>=32; measured regression r15).
// GEMM kernels MUST carry __launch_bounds__(256, 2): without it ptxas used
// 152 regs -> 1 CTA/SM -> 1.13x regression (round 16).
// ---------------------------------------------------------------------------
__device__ __forceinline__ uint32_t f2tf32(float x) {
    uint32_t r;
    asm("cvt.rna.tf32.f32 %0, %1;" : "=r"(r) : "f"(x));
    return r;
}

__device__ __forceinline__ float ex2(float x) {
    float r;
    asm("ex2.approx.f32 %0, %1;" : "=f"(r) : "f"(x));
    return r;
}

__device__ __forceinline__ uint32_t smaddr(const void* p) {
    return (uint32_t)__cvta_generic_to_shared(p);
}

__device__ __forceinline__ void ldsm4(uint32_t& r0, uint32_t& r1,
                                      uint32_t& r2, uint32_t& r3, uint32_t a) {
    asm volatile("ldmatrix.sync.aligned.m8n8.x4.shared.b16 {%0,%1,%2,%3}, [%4];"
                 : "=r"(r0), "=r"(r1), "=r"(r2), "=r"(r3) : "r"(a));
}

__device__ __forceinline__ void mma_tf32(float* c,
                                         uint32_t a0, uint32_t a1, uint32_t a2, uint32_t a3,
                                         uint32_t b0, uint32_t b1) {
    asm("mma.sync.aligned.m16n8k8.row.col.f32.tf32.tf32.f32 "
        "{%0,%1,%2,%3}, {%4,%5,%6,%7}, {%8,%9}, {%0,%1,%2,%3};"
        : "+f"(c[0]), "+f"(c[1]), "+f"(c[2]), "+f"(c[3])
        : "r"(a0), "r"(a1), "r"(a2), "r"(a3), "r"(b0), "r"(b1));
}

__device__ __forceinline__ void mma_bf16(float* c,
                                         uint32_t a0, uint32_t a1, uint32_t a2, uint32_t a3,
                                         uint32_t b0, uint32_t b1) {
    asm("mma.sync.aligned.m16n8k16.row.col.f32.bf16.bf16.f32 "
        "{%0,%1,%2,%3}, {%4,%5,%6,%7}, {%8,%9}, {%0,%1,%2,%3};"
        : "+f"(c[0]), "+f"(c[1]), "+f"(c[2]), "+f"(c[3])
        : "r"(a0), "r"(a1), "r"(a2), "r"(a3), "r"(b0), "r"(b1));
}

__device__ __forceinline__ void split2(float e, float o, uint32_t& hi, uint32_t& lo) {
    __nv_bfloat162 h = __floats2bfloat162_rn(e, o);
    float he = __low2float(h), ho = __high2float(h);
    __nv_bfloat162 l = __floats2bfloat162_rn(e - he, o - ho);
    hi = *reinterpret_cast<uint32_t*>(&h);
    lo = *reinterpret_cast<uint32_t*>(&l);
}

// ---------------------------------------------------------------------------
// Prepack GEMM inputs q/k/v [M][K] fp32 -> hi/lo [M][K/2] u32.  z selects.
// ---------------------------------------------------------------------------
__global__ void prepack_in_kernel(const float* __restrict__ Aq,
                                  const float* __restrict__ Ak,
                                  const float* __restrict__ Av)
{
    const int z = blockIdx.z;
    const float* A = (z == 0) ? Aq : (z == 1) ? Ak : Av;
    uint32_t* hi = (z == 0) ? g_xq_h : (z == 1) ? g_xk_h : g_xv_h;
    uint32_t* lo = (z == 0) ? g_xq_l : (z == 1) ? g_xk_l : g_xv_l;
    int idx = blockIdx.x * blockDim.x + threadIdx.x;
    if (idx >= BT_ * K2_) return;
    float2 v = *(const float2*)(A + (size_t)idx * 2);
    uint32_t h, l;
    split2(v.x, v.y, h, l);
    hi[idx] = h;
    lo[idx] = l;
}

// ---------------------------------------------------------------------------
// Prepack QKV weights W [K][N] fp32 -> hi/lo [N][K/2] u32.  z selects q/k/v.
// ---------------------------------------------------------------------------
__global__ void prepack_wqkv_kernel(const float* __restrict__ Wq,
                                    const float* __restrict__ Wk,
                                    const float* __restrict__ Wv)
{
    const int z = blockIdx.z;
    const float* W = (z == 0) ? Wq : (z == 1) ? Wk : Wv;
    uint32_t* hi = (z == 0) ? g_wq_hi : (z == 1) ? g_wk_hi : g_wv_hi;
    uint32_t* lo = (z == 0) ? g_wq_lo : (z == 1) ? g_wk_lo : g_wv_lo;
    int idx = blockIdx.x * blockDim.x + threadIdx.x;
    if (idx >= NDH_ * K2_) return;
    int kp = idx & (K2_ - 1);
    int n  = idx >> 9;
    float e = W[(size_t)(2 * kp) * NDH_ + n];
    float o = W[(size_t)(2 * kp + 1) * NDH_ + n];
    uint32_t h, l;
    split2(e, o, h, l);
    hi[(size_t)n * K2_ + kp] = h;
    lo[(size_t)n * K2_ + kp] = l;
}

// ---------------------------------------------------------------------------
// Prepack w_projection [N, D, H] -> hi/lo [d][(n,h)/2] u32
// ---------------------------------------------------------------------------
__global__ void prepack_wpt_kernel(const float* __restrict__ wp)
{
    int idx = blockIdx.x * blockDim.x + threadIdx.x;
    if (idx >= D_ * K2_) return;
    int kp = idx & (K2_ - 1);
    int d  = idx >> 9;
    int n  = kp >> 5;
    int hp = kp & 31;
    const float* base = wp + ((size_t)n * D_ + d) * HD_ + 2 * hp;
    float e = base[0], o = base[1];
    uint32_t h, l;
    split2(e, o, h, l);
    g_wp_hi[(size_t)d * K2_ + kp] = h;
    g_wp_lo[(size_t)d * K2_ + kp] = l;
}

// ---------------------------------------------------------------------------
// Prepack V: [bn][t][h] fp32 -> [bn][h][t] tf32 bits (transpose).
// ---------------------------------------------------------------------------
__global__ __launch_bounds__(256)
void prepack_v_kernel()
{
    __shared__ float sm[64][65];
    const int bn = blockIdx.y;
    const int tt = blockIdx.x;          // t-tile of 64
    const int tid = threadIdx.x;
    const float* Vg = g_v + ((size_t)bn * T_ + tt * 64) * HD_;

    #pragma unroll
    for (int i = 0; i < 4; i++) {
        int lin = tid + i * 256;
        int r = lin >> 4, c4 = (lin & 15) << 2;
        float4 v = *(const float4*)(Vg + r * HD_ + c4);
        sm[r][c4 + 0] = v.x; sm[r][c4 + 1] = v.y;
        sm[r][c4 + 2] = v.z; sm[r][c4 + 3] = v.w;
    }
    __syncthreads();

    #pragma unroll
    for (int i = 0; i < 4; i++) {
        int lin = tid + i * 256;
        int h = lin >> 4, t4 = (lin & 15) << 2;
        float4 v;
        v.x = __uint_as_float(f2tf32(sm[t4 + 0][h]));
        v.y = __uint_as_float(f2tf32(sm[t4 + 1][h]));
        v.z = __uint_as_float(f2tf32(sm[t4 + 2][h]));
        v.w = __uint_as_float(f2tf32(sm[t4 + 3][h]));
        *(float4*)(g_vt + ((size_t)bn * HD_ + h) * T_ + tt * 64 + t4) = v;
    }
}

// ---------------------------------------------------------------------------
// bf16-split tensor-core GEMM: ALL operands prepacked hi/lo [m][kp] u32.
// Register LDG prefetch (4x LDG.128) -> STS.128, double-buffered smem,
// one syncthreads per k-tile, ldmatrix fragments, zero conversion in loop.
// MODE 0: tf32 bits out [b,n,t,h], scaled    (Q with QSCALE, K with 1.0)
// MODE 1: fp32 out [M][Ncols] row-major       (out-proj)
// MODE 2: fp32 out [b,n,t,h]                  (V)
// ---------------------------------------------------------------------------
template<int MODE>
__device__ __forceinline__ void gemm_core(const uint32_t* __restrict__ Ahi,
                                          const uint32_t* __restrict__ Alo,
                                          const uint32_t* __restrict__ Bhi,
                                          const uint32_t* __restrict__ Blo,
                                          const float* __restrict__ bias,
                                          float* __restrict__ C,
                                          float scale,
                                          int M, int K, int Ncols)
{
    __shared__ uint32_t AsHi[2][128 * 12];
    __shared__ uint32_t AsLo[2][128 * 12];
    __shared__ uint32_t BsHi[2][128 * 12];
    __shared__ uint32_t BsLo[2][128 * 12];

    const int tid  = threadIdx.x;
    const int warp = tid >> 5;
    const int lane = tid & 31;
    const int g    = lane >> 2;
    const int tig  = lane & 3;
    const int wm   = warp >> 2;
    const int wn   = warp & 3;
    const int m0   = blockIdx.y * 128;
    const int n0   = blockIdx.x * 128;
    const int Kp   = K >> 1;

    const int lrow  = tid >> 1;
    const int lhalf = tid & 1;

    const int arow = (lane & 7) + ((lane >> 3) & 1) * 8;
    const int akp  = (lane >> 4) * 4;
    const int brow = (lane & 7) + ((lane >> 4) & 1) * 8;
    const int bkp  = ((lane >> 3) & 1) * 4;

    const uint32_t ash = smaddr(AsHi), asl = smaddr(AsLo);
    const uint32_t bsh = smaddr(BsHi), bsl = smaddr(BsLo);
    const uint32_t a_fo = ((arow) * 12 + akp) * 4;
    const uint32_t b_fo = ((brow) * 12 + bkp) * 4;

    const size_t a_base = (size_t)(m0 + lrow) * Kp + lhalf * 4;
    const size_t b_base = (size_t)(n0 + lrow) * Kp + lhalf * 4;
    const int    soff   = lrow * 12 + lhalf * 4;

    float acc[4][4][4];
    #pragma unroll
    for (int i = 0; i < 4; i++)
        #pragma unroll
        for (int j = 0; j < 4; j++)
            #pragma unroll
            for (int e = 0; e < 4; e++)
                acc[i][j][e] = 0.0f;

    uint4 arh, arl, brh, brl;

    auto gload = [&](int k0) {
        const int kq = k0 >> 1;
        arh = *(const uint4*)(Ahi + a_base + kq);
        arl = *(const uint4*)(Alo + a_base + kq);
        brh = *(const uint4*)(Bhi + b_base + kq);
        brl = *(const uint4*)(Blo + b_base + kq);
    };

    auto sstore = [&](int st) {
        *(uint4*)&AsHi[st][soff] = arh;
        *(uint4*)&AsLo[st][soff] = arl;
        *(uint4*)&BsHi[st][soff] = brh;
        *(uint4*)&BsLo[st][soff] = brl;
    };

    auto compute = [&](int st) {
        const uint32_t sto = st * (128 * 12 * 4);
        uint32_t bh[4][2], bl[4][2];
        #pragma unroll
        for (int nt2 = 0; nt2 < 2; nt2++) {
            const uint32_t ro = (wn * 32 + nt2 * 16) * 12 * 4;
            ldsm4(bh[nt2*2][0], bh[nt2*2][1], bh[nt2*2+1][0], bh[nt2*2+1][1],
                  bsh + sto + ro + b_fo);
            ldsm4(bl[nt2*2][0], bl[nt2*2][1], bl[nt2*2+1][0], bl[nt2*2+1][1],
                  bsl + sto + ro + b_fo);
        }
        #pragma unroll
        for (int mt = 0; mt < 4; mt++) {
            const uint32_t ro = (wm * 64 + mt * 16) * 12 * 4;
            uint32_t ah0, ah1, ah2, ah3, al0, al1, al2, al3;
            ldsm4(ah0, ah1, ah2, ah3, ash + sto + ro + a_fo);
            ldsm4(al0, al1, al2, al3, asl + sto + ro + a_fo);
            #pragma unroll
            for (int nt = 0; nt < 4; nt++)
                mma_bf16(acc[mt][nt], ah0, ah1, ah2, ah3, bh[nt][0], bh[nt][1]);
            #pragma unroll
            for (int nt = 0; nt < 4; nt++)
                mma_bf16(acc[mt][nt], ah0, ah1, ah2, ah3, bl[nt][0], bl[nt][1]);
            #pragma unroll
            for (int nt = 0; nt < 4; nt++)
                mma_bf16(acc[mt][nt], al0, al1, al2, al3, bh[nt][0], bh[nt][1]);
        }
    };

    gload(0);
    sstore(0);
    __syncthreads();

    int st = 0;
    for (int k0 = 16; k0 < K; k0 += 16) {
        gload(k0);          // prefetch next tile (LDGs fly under MMAs)
        compute(st);
        sstore(st ^ 1);
        __syncthreads();
        st ^= 1;
    }
    compute(st);

    #pragma unroll
    for (int mt = 0; mt < 4; mt++) {
        #pragma unroll
        for (int nt = 0; nt < 4; nt++) {
            const int cbase = n0 + wn * 32 + nt * 8 + tig * 2;
            const int mg = m0 + wm * 64 + mt * 16 + g;
            #pragma unroll
            for (int e = 0; e < 4; e++) {
                const int m  = mg + ((e >= 2) ? 8 : 0);
                const int cc = cbase + (e & 1);
                float val = acc[mt][nt][e] + bias[cc];
                if (MODE == 0) {
                    int b = m >> 11, t = m & (T_ - 1);
                    int n = cc >> 6, h = cc & 63;
                    C[(((size_t)b * NH_ + n) * T_ + t) * HD_ + h] =
                        __uint_as_float(f2tf32(val * scale));
                } else if (MODE == 2) {
                    int b = m >> 11, t = m & (T_ - 1);
                    int n = cc >> 6, h = cc & 63;
                    C[(((size_t)b * NH_ + n) * T_ + t) * HD_ + h] = val;
                } else {
                    C[(size_t)m * Ncols + cc] = val;
                }
            }
        }
    }
}

// Batched QKV projection: z=0 Q (tf32 bits, prescaled), z=1 K, z=2 V fp32
__global__ __launch_bounds__(256, 2)
void gemm_qkv_kernel(const float* __restrict__ bq, const float* __restrict__ bk,
                     const float* __restrict__ bv)
{
    const int z = blockIdx.z;
    if (z == 0)
        gemm_core<0>(g_xq_h, g_xq_l, g_wq_hi, g_wq_lo, bq, g_qt, QSCALE, BT_, D_, NDH_);
    else if (z == 1)
        gemm_core<0>(g_xk_h, g_xk_l, g_wk_hi, g_wk_lo, bk, g_kt, 1.0f, BT_, D_, NDH_);
    else
        gemm_core<2>(g_xv_h, g_xv_l, g_wv_hi, g_wv_lo, bv, g_v, 1.0f, BT_, D_, NDH_);
}

__global__ __launch_bounds__(256, 2)
void gemm_out_kernel(const float* __restrict__ bias, float* __restrict__ C)
{
    gemm_core<1>(g_oh, g_ol, g_wp_hi, g_wp_lo, bias, C, 1.0f, BT_, NDH_, D_);
}

// ---------------------------------------------------------------------------
// tf32 flash attention, prepacked inputs + ldmatrix fragments (r14, passing).
// ---------------------------------------------------------------------------
__global__ __launch_bounds__(256, 2)
void attn_tc_kernel()
{
    extern __shared__ float smx[];
    float* Kt  = smx;                 // [64][68]
    float* VtT = smx + 64 * 68;       // [64][68]
    float* Pw  = VtT + 64 * 68;       // [128][68]

    const int tid  = threadIdx.x;
    const int warp = tid >> 5;
    const int lane = tid & 31;
    const int g    = lane >> 2;
    const int tig  = lane & 3;
    const int bn   = blockIdx.y;
    const int b    = bn / NH_;
    const int n    = bn % NH_;
    const int q0   = blockIdx.x * 128;
    const int wrow = warp * 16;

    const uint32_t kt_b = smaddr(Kt);
    const uint32_t vt_b = smaddr(VtT);
    const uint32_t pw_b = smaddr(Pw);

    const int arow = (lane & 7) + ((lane >> 3) & 1) * 8;
    const int ako  = (lane >> 4) * 4;
    const int brow = (lane & 7) + ((lane >> 4) & 1) * 8;
    const int bko  = ((lane >> 3) & 1) * 4;
    const uint32_t a_fo = (uint32_t)(arow * 68 + ako) * 4;
    const uint32_t b_fo = (uint32_t)(brow * 68 + bko) * 4;

    // persistent Q fragments: direct LDG from prescaled tf32 global
    uint32_t qf[8][4];
    {
        const float* Q0 = g_qt + ((size_t)bn * T_ + q0 + wrow + g) * HD_;
        const float* Q1 = Q0 + 8 * HD_;
        #pragma unroll
        for (int k8 = 0; k8 < 8; k8++) {
            qf[k8][0] = __float_as_uint(Q0[k8 * 8 + tig    ]);
            qf[k8][1] = __float_as_uint(Q1[k8 * 8 + tig    ]);
            qf[k8][2] = __float_as_uint(Q0[k8 * 8 + tig + 4]);
            qf[k8][3] = __float_as_uint(Q1[k8 * 8 + tig + 4]);
        }
    }

    const float* Kg  = g_kt + (size_t)bn * T_ * HD_;
    const float* Vtg = g_vt + (size_t)bn * HD_ * T_;

    float of[8][4];
    #pragma unroll
    for (int i = 0; i < 8; i++)
        #pragma unroll
        for (int e = 0; e < 4; e++) of[i][e] = 0.0f;
    float m0r = -1e30f, m1r = -1e30f;
    float l0r = 0.0f,   l1r = 0.0f;

    for (int s0 = 0; s0 < T_; s0 += 64) {
        __syncthreads();
        #pragma unroll
        for (int i = 0; i < 4; i++) {
            int idx = tid + i * 256;
            int r = idx >> 4, c4 = (idx & 15) << 2;
            *(float4*)&Kt[r * 68 + c4]  = *(const float4*)(Kg  + (size_t)(s0 + r) * HD_ + c4);
            *(float4*)&VtT[r * 68 + c4] = *(const float4*)(Vtg + (size_t)r * T_ + s0 + c4);
        }
        __syncthreads();

        // S = Q @ K^T (tf32), fragments via ldmatrix
        float sacc[8][4];
        #pragma unroll
        for (int i = 0; i < 8; i++)
            #pragma unroll
            for (int e = 0; e < 4; e++) sacc[i][e] = 0.0f;
        #pragma unroll
        for (int k8 = 0; k8 < 8; k8++) {
            #pragma unroll
            for (int nt2 = 0; nt2 < 4; nt2++) {
                const uint32_t off = (uint32_t)(nt2 * 16 * 68 + k8 * 8) * 4;
                uint32_t b0, b1, b2, b3;
                ldsm4(b0, b1, b2, b3, kt_b + off + b_fo);
                mma_tf32(sacc[2*nt2],   qf[k8][0], qf[k8][1], qf[k8][2], qf[k8][3], b0, b1);
                mma_tf32(sacc[2*nt2+1], qf[k8][0], qf[k8][1], qf[k8][2], qf[k8][3], b2, b3);
            }
        }

        // online softmax (base-2)
        float mx0 = -1e30f, mx1 = -1e30f;
        #pragma unroll
        for (int nt = 0; nt < 8; nt++) {
            mx0 = fmaxf(mx0, fmaxf(sacc[nt][0], sacc[nt][1]));
            mx1 = fmaxf(mx1, fmaxf(sacc[nt][2], sacc[nt][3]));
        }
        mx0 = fmaxf(mx0, __shfl_xor_sync(0xffffffffu, mx0, 1));
        mx0 = fmaxf(mx0, __shfl_xor_sync(0xffffffffu, mx0, 2));
        mx1 = fmaxf(mx1, __shfl_xor_sync(0xffffffffu, mx1, 1));
        mx1 = fmaxf(mx1, __shfl_xor_sync(0xffffffffu, mx1, 2));
        float nm0 = fmaxf(m0r, mx0), nm1 = fmaxf(m1r, mx1);
        float cr0 = ex2(m0r - nm0), cr1 = ex2(m1r - nm1);
        m0r = nm0; m1r = nm1;

        float sum0 = 0.0f, sum1 = 0.0f;
        #pragma unroll
        for (int nt = 0; nt < 8; nt++) {
            sacc[nt][0] = ex2(sacc[nt][0] - nm0);
            sacc[nt][1] = ex2(sacc[nt][1] - nm0);
            sacc[nt][2] = ex2(sacc[nt][2] - nm1);
            sacc[nt][3] = ex2(sacc[nt][3] - nm1);
            sum0 += sacc[nt][0] + sacc[nt][1];
            sum1 += sacc[nt][2] + sacc[nt][3];
        }
        sum0 += __shfl_xor_sync(0xffffffffu, sum0, 1);
        sum0 += __shfl_xor_sync(0xffffffffu, sum0, 2);
        sum1 += __shfl_xor_sync(0xffffffffu, sum1, 1);
        sum1 += __shfl_xor_sync(0xffffffffu, sum1, 2);
        l0r = l0r * cr0 + sum0;
        l1r = l1r * cr1 + sum1;
        #pragma unroll
        for (int nt = 0; nt < 8; nt++) {
            of[nt][0] *= cr0; of[nt][1] *= cr0;
            of[nt][2] *= cr1; of[nt][3] *= cr1;
        }

        // store P (tf32 bits) into this warp's own rows of Pw
        #pragma unroll
        for (int nt = 0; nt < 8; nt++) {
            float2 v01, v23;
            v01.x = __uint_as_float(f2tf32(sacc[nt][0]));
            v01.y = __uint_as_float(f2tf32(sacc[nt][1]));
            v23.x = __uint_as_float(f2tf32(sacc[nt][2]));
            v23.y = __uint_as_float(f2tf32(sacc[nt][3]));
            *(float2*)&Pw[(wrow + g    ) * 68 + nt * 8 + tig * 2] = v01;
            *(float2*)&Pw[(wrow + g + 8) * 68 + nt * 8 + tig * 2] = v23;
        }
        __syncwarp();

        // O += P @ V
        #pragma unroll
        for (int k8 = 0; k8 < 8; k8++) {
            uint32_t a0, a1, a2, a3;
            ldsm4(a0, a1, a2, a3,
                  pw_b + (uint32_t)(wrow * 68 * 4) + (uint32_t)(k8 * 32) + a_fo);
            #pragma unroll
            for (int nt2 = 0; nt2 < 4; nt2++) {
                const uint32_t off = (uint32_t)(nt2 * 16 * 68 + k8 * 8) * 4;
                uint32_t v0, v1, v2, v3;
                ldsm4(v0, v1, v2, v3, vt_b + off + b_fo);
                mma_tf32(of[2*nt2],   a0, a1, a2, a3, v0, v1);
                mma_tf32(of[2*nt2+1], a0, a1, a2, a3, v2, v3);
            }
        }
    }

    // epilogue: normalize, pack bf16 hi/lo pairs, write [m][(n,h)/2]
    const float inv0 = 1.0f / l0r;
    const float inv1 = 1.0f / l1r;
    const int t0 = q0 + wrow + g;
    const size_t m0row = (size_t)(b * T_ + t0) * K2_;
    const size_t m1row = (size_t)(b * T_ + t0 + 8) * K2_;
    #pragma unroll
    for (int nt = 0; nt < 8; nt++) {
        const int kp = n * 32 + nt * 4 + tig;
        uint32_t h0, l0, h1, l1;
        split2(of[nt][0] * inv0, of[nt][1] * inv0, h0, l0);
        split2(of[nt][2] * inv1, of[nt][3] * inv1, h1, l1);
        g_oh[m0row + kp] = h0;  g_ol[m0row + kp] = l0;
        g_oh[m1row + kp] = h1;  g_ol[m1row + kp] = l1;
    }
}

// ---------------------------------------------------------------------------
// Launch
// Inputs: 0:q 1:v 2:k 3:w_query 4:b_query 5:w_value 6:b_value 7:w_key 8:b_key
//         9:w_projection 10:b_projection
// ---------------------------------------------------------------------------
extern "C" void kernel_launch(void* const* d_in, const int* in_sizes, int n_in,
                              void* d_out, int out_size)
{
    const float* q_in = (const float*)d_in[0];
    const float* v_in = (const float*)d_in[1];
    const float* k_in = (const float*)d_in[2];
    const float* w_q  = (const float*)d_in[3];
    const float* b_q  = (const float*)d_in[4];
    const float* w_v  = (const float*)d_in[5];
    const float* b_v  = (const float*)d_in[6];
    const float* w_k  = (const float*)d_in[7];
    const float* b_k  = (const float*)d_in[8];
    const float* w_p  = (const float*)d_in[9];
    const float* b_p  = (const float*)d_in[10];
    float* out = (float*)d_out;

    const int ATTN_SMEM = (64 * 68 + 64 * 68 + 128 * 68) * 4;   // 69632 B
    cudaFuncSetAttribute(attn_tc_kernel,
                         cudaFuncAttributeMaxDynamicSharedMemorySize, ATTN_SMEM);

    // 1. prepack weights + inputs (bf16 hi/lo pairs)
    dim3 wgrid((NDH_ * K2_) / 256, 1, 3);
    prepack_wqkv_kernel<<<wgrid, 256>>>(w_q, w_k, w_v);
    prepack_wpt_kernel<<<(D_ * K2_) / 256, 256>>>(w_p);
    dim3 igrid((BT_ * K2_) / 256, 1, 3);
    prepack_in_kernel<<<igrid, 256>>>(q_in, k_in, v_in);

    // 2. QKV projections (all operands prepacked; register LDG prefetch)
    dim3 ggrid(NDH_ / 128, BT_ / 128, 3);
    gemm_qkv_kernel<<<ggrid, 256>>>(b_q, b_k, b_v);

    // 3. prepack V (transpose to [bn][h][t] tf32 bits)
    dim3 vgrid(T_ / 64, BN_);
    prepack_v_kernel<<<vgrid, 256>>>();

    // 4. attention (tf32, ldmatrix fragments, packed bf16 output)
    dim3 agrid(T_ / 128, BN_);
    attn_tc_kernel<<<agrid, 256, ATTN_SMEM>>>();

    // 5. output projection
    dim3 pgrid(D_ / 128, BT_ / 128);
    gemm_out_kernel<<<pgrid, 256>>>(b_p, out);
}